// round 11
// baseline (speedup 1.0000x reference)
#include <cuda_runtime.h>
#include <cstdint>

#define BATCH 32
#define CH    256
#define HH    56
#define WW    56
#define HW    3136
#define KK2   2304      // CH*9
#define MEXP  8

#define BM 256          // o per CTA (full output-channel range)
#define BN 64           // pixels per CTA (49*64 = 3136 exact)
#define BK 32           // k per chunk
#define NCHUNK (KK2 / BK)   // 72

// swizzled smem: row = 32 tf32 = 128B; 16B-group g stored at g ^ (row&7)
#define ATILE  (BM * 128)       // 32768
#define BTILE  (BN * 128)       // 8192
#define STAGE  (ATILE + BTILE)  // 40960
#define NSTAGE 2
#define SMEM_BYTES (NSTAGE * STAGE)   // 81920

// Scratch
__device__ float    g_gap[BATCH * CH];
__device__ float    g_alpha[BATCH * MEXP];
__device__ float    g_biasc[BATCH * CH];
__device__ uint32_t g_wt[(size_t)BATCH * CH * KK2];   // combined weights, tf32 [b][o][k]
__device__ uint32_t g_xt[(size_t)BATCH * CH * HW];    // x as tf32

// conv offset per kernel-position r: (r/3-1)*56 + (r%3-1)
__constant__ int c_doff[9] = { -57, -56, -55, -1, 0, 1, 55, 56, 57 };

// ---------------- helpers ----------------
__device__ __forceinline__ uint32_t smem_u32(const void* p) {
    uint32_t a;
    asm("{ .reg .u64 t; cvta.to.shared.u64 t, %1; cvt.u32.u64 %0, t; }" : "=r"(a) : "l"(p));
    return a;
}
__device__ __forceinline__ uint32_t f2tf32(float f) {
    uint32_t r; asm("cvt.rna.tf32.f32 %0, %1;" : "=r"(r) : "f"(f)); return r;
}
__device__ __forceinline__ void ldsm4(uint32_t& r0, uint32_t& r1, uint32_t& r2, uint32_t& r3,
                                      uint32_t addr) {
    asm volatile("ldmatrix.sync.aligned.m8n8.x4.shared.b16 {%0,%1,%2,%3}, [%4];"
                 : "=r"(r0), "=r"(r1), "=r"(r2), "=r"(r3) : "r"(addr));
}
__device__ __forceinline__ void mma_tf32(float* c, const uint32_t* a, uint32_t b0, uint32_t b1) {
    asm volatile(
        "mma.sync.aligned.m16n8k8.row.col.f32.tf32.tf32.f32 "
        "{%0,%1,%2,%3}, {%4,%5,%6,%7}, {%8,%9}, {%0,%1,%2,%3};"
        : "+f"(c[0]), "+f"(c[1]), "+f"(c[2]), "+f"(c[3])
        : "r"(a[0]), "r"(a[1]), "r"(a[2]), "r"(a[3]), "r"(b0), "r"(b1));
}
__device__ __forceinline__ void cpasync16(uint32_t dst, const void* src) {
    asm volatile("cp.async.cg.shared.global [%0], [%1], 16;" :: "r"(dst), "l"(src) : "memory");
}
__device__ __forceinline__ void cpasync4z(uint32_t dst, const void* src, uint32_t srcsz) {
    asm volatile("cp.async.ca.shared.global [%0], [%1], 4, %2;"
                 :: "r"(dst), "l"(src), "r"(srcsz) : "memory");
}

// ---------------------------------------------------------------------------
// 1) Global average pool
// ---------------------------------------------------------------------------
__global__ void gap_kernel(const float* __restrict__ x) {
    int bc = blockIdx.x;
    const float* p = x + (size_t)bc * HW;
    float s = 0.f;
    for (int i = threadIdx.x; i < HW; i += 128) s += p[i];
    __shared__ float sm[4];
    #pragma unroll
    for (int off = 16; off; off >>= 1) s += __shfl_down_sync(0xffffffffu, s, off);
    if ((threadIdx.x & 31) == 0) sm[threadIdx.x >> 5] = s;
    __syncthreads();
    if (threadIdx.x == 0)
        g_gap[bc] = (sm[0] + sm[1] + sm[2] + sm[3]) * (1.f / (float)HW);
}

// ---------------------------------------------------------------------------
// 2) Gate softmax + combined bias
// ---------------------------------------------------------------------------
__global__ void gate_kernel(const float* __restrict__ gate_w,
                            const float* __restrict__ gate_b,
                            const float* __restrict__ bias) {
    __shared__ float lg[BATCH][MEXP];
    __shared__ float al[BATCH][MEXP];
    int t = threadIdx.x;
    int b = t >> 3, m = t & 7;
    float acc = gate_b[m];
    const float* gp = &g_gap[b * CH];
    const float* gw = &gate_w[m * CH];
    for (int i = 0; i < CH; i++) acc += gp[i] * gw[i];
    lg[b][m] = acc;
    __syncthreads();
    if (t < BATCH) {
        float mx = lg[t][0];
        #pragma unroll
        for (int j = 1; j < MEXP; j++) mx = fmaxf(mx, lg[t][j]);
        float e[MEXP], s = 0.f;
        #pragma unroll
        for (int j = 0; j < MEXP; j++) { e[j] = expf(lg[t][j] - mx); s += e[j]; }
        float inv = 1.f / s;
        #pragma unroll
        for (int j = 0; j < MEXP; j++) { al[t][j] = e[j] * inv; g_alpha[t * MEXP + j] = e[j] * inv; }
    }
    __syncthreads();
    for (int b2 = 0; b2 < BATCH; b2++) {
        float s = 0.f;
        #pragma unroll
        for (int j = 0; j < MEXP; j++) s += al[b2][j] * bias[j * CH + t];
        g_biasc[b2 * CH + t] = s;
    }
}

// ---------------------------------------------------------------------------
// 3) Combine experts -> tf32
// ---------------------------------------------------------------------------
__global__ void combine_kernel(const float* __restrict__ weight) {
    int b = blockIdx.y;
    size_t i4 = (size_t)blockIdx.x * 256 + threadIdx.x;
    float a[MEXP];
    #pragma unroll
    for (int m = 0; m < MEXP; m++) a[m] = g_alpha[b * MEXP + m];
    float4 acc = make_float4(0.f, 0.f, 0.f, 0.f);
    #pragma unroll
    for (int m = 0; m < MEXP; m++) {
        const float4 v = ((const float4*)(weight + (size_t)m * CH * KK2))[i4];
        acc.x += a[m] * v.x; acc.y += a[m] * v.y;
        acc.z += a[m] * v.z; acc.w += a[m] * v.w;
    }
    uint4 o;
    o.x = f2tf32(acc.x); o.y = f2tf32(acc.y);
    o.z = f2tf32(acc.z); o.w = f2tf32(acc.w);
    ((uint4*)(g_wt + (size_t)b * CH * KK2))[i4] = o;
}

// ---------------------------------------------------------------------------
// 3b) x -> tf32
// ---------------------------------------------------------------------------
__global__ void xsplit_kernel(const float* __restrict__ x) {
    size_t i4 = (size_t)blockIdx.x * 256 + threadIdx.x;
    float4 v = ((const float4*)x)[i4];
    uint4 o;
    o.x = f2tf32(v.x); o.y = f2tf32(v.y);
    o.z = f2tf32(v.z); o.w = f2tf32(v.w);
    ((uint4*)g_xt)[i4] = o;
}

// ---------------------------------------------------------------------------
// 4) Conv GEMM: tf32 mma.sync m16n8k8. Tile 256(o) x 64(pix) x 32(k).
//    grid (49, 32); 8 warps, warp tile m32 x n64. 2-stage, 2 CTAs/SM.
// ---------------------------------------------------------------------------
__global__ void __launch_bounds__(256, 2)
conv_mma_kernel(float* __restrict__ out) {
    extern __shared__ char smem[];
    const uint32_t sbase = smem_u32(smem);
    const int tid  = threadIdx.x;
    const int wid  = tid >> 5;
    const int lane = tid & 31;

    const int b  = blockIdx.y;
    const int p0 = blockIdx.x * BN;

    // ---- A producer: thread -> o-row tid; 8 x cp.async.16, swizzled
    const uint32_t* wRow = g_wt + ((size_t)(b * CH) + tid) * KK2;
    const uint32_t ars = (uint32_t)(tid & 7);
    uint32_t aDstG[8];
    #pragma unroll
    for (int q = 0; q < 8; q++)
        aDstG[q] = (uint32_t)tid * 128 + (((uint32_t)q ^ ars) << 4);

    // ---- B producer: thread -> pixel row tid>>2, k-quarter tid&3 (8 k's)
    const int prow = tid >> 2;
    const int kq   = tid & 3;
    const int pp   = p0 + prow;
    uint32_t vmask;
    {
        int hjv = pp / WW, wjv = pp - (pp / WW) * WW;
        uint32_t m = 0;
        #pragma unroll
        for (int r = 0; r < 9; r++) {
            int ih = hjv + r / 3 - 1;
            int iw = wjv + r % 3 - 1;
            if ((unsigned)ih < HH && (unsigned)iw < WW) m |= (1u << r);
        }
        vmask = m;
    }
    // incremental state for first k of this thread's 8-k strip
    int rst0, coff0;
    {
        int k0 = kq * 8;
        int c0 = k0 / 9;
        rst0  = k0 - 9 * c0;
        coff0 = c0 * HW;
    }
    const uint32_t* xb = g_xt + (size_t)b * CH * HW;
    // B smem dst: prow*128 + swizzled group; group g = (kq*8+i)>>2
    const uint32_t bRowDst = ATILE + (uint32_t)prow * 128;
    const uint32_t prs = (uint32_t)(prow & 7);

    // ---- consumer addresses
    const uint32_t ls  = (uint32_t)(lane & 7);
    const uint32_t aHi = (uint32_t)(lane >> 4);      // 0/1
    const uint32_t bHi = (uint32_t)(lane >> 3);      // 0..3
    const uint32_t aRow0 = (uint32_t)(wid * 32 + (lane & 15)) * 128;       // m-half 0
    const uint32_t aRow1 = aRow0 + 16 * 128;                                // m-half 1

    float acc[2][8][4];
    #pragma unroll
    for (int h = 0; h < 2; h++)
        #pragma unroll
        for (int j = 0; j < 8; j++)
            #pragma unroll
            for (int q = 0; q < 4; q++) acc[h][j][q] = 0.f;

    auto issueStage = [&](int chunk, int s) {
        const uint32_t stg = sbase + s * STAGE;
        // A: 32 words per row
        const uint32_t* srcA = wRow + chunk * BK;
        #pragma unroll
        for (int q = 0; q < 8; q++) cpasync16(stg + aDstG[q], srcA + q * 4);
        // B: 8 k-values for this thread's pixel
        int rr = rst0, cf = coff0;
        #pragma unroll
        for (int i = 0; i < 8; i++) {
            uint32_t ok = (vmask >> rr) & 1u;
            const uint32_t* src = ok ? (xb + cf + c_doff[rr] + pp) : xb;
            int ki = kq * 8 + i;
            uint32_t dst = stg + bRowDst + (((uint32_t)(ki >> 2) ^ prs) << 4)
                         + (uint32_t)(ki & 3) * 4;
            cpasync4z(dst, src, ok ? 4u : 0u);
            rr++;
            if (rr == 9) { rr = 0; cf += HW; }
        }
        asm volatile("cp.async.commit_group;" ::: "memory");
        // advance state by BK=32 k: +3 full channels and +5 r (wrap adds one more)
        rst0 += 5;
        if (rst0 >= 9) { rst0 -= 9; coff0 += 4 * HW; }
        else coff0 += 3 * HW;
    };

    // ---- prologue ----
    issueStage(0, 0);
    issueStage(1, 1);

    for (int c0 = 0; c0 < NCHUNK; c0++) {
        const int s = c0 & 1;
        if (c0 + 1 < NCHUNK)
            asm volatile("cp.async.wait_group 1;" ::: "memory");
        else
            asm volatile("cp.async.wait_group 0;" ::: "memory");
        __syncthreads();

        const uint32_t stg = sbase + s * STAGE;
        const uint32_t sB  = stg + ATILE;

        #pragma unroll
        for (int t = 0; t < 2; t++) {
            uint32_t a[2][2][4];   // [m-half][k8 lo/hi]
            ldsm4(a[0][0][0], a[0][0][1], a[0][0][2], a[0][0][3],
                  stg + aRow0 + (((4u * t + 0 + aHi) ^ ls) << 4));
            ldsm4(a[0][1][0], a[0][1][1], a[0][1][2], a[0][1][3],
                  stg + aRow0 + (((4u * t + 2 + aHi) ^ ls) << 4));
            ldsm4(a[1][0][0], a[1][0][1], a[1][0][2], a[1][0][3],
                  stg + aRow1 + (((4u * t + 0 + aHi) ^ ls) << 4));
            ldsm4(a[1][1][0], a[1][1][1], a[1][1][2], a[1][1][3],
                  stg + aRow1 + (((4u * t + 2 + aHi) ^ ls) << 4));
            #pragma unroll
            for (int half = 0; half < 2; half++) {
                uint32_t bb[4][4];
                #pragma unroll
                for (int q = 0; q < 4; q++) {
                    int nb = half * 4 + q;
                    uint32_t rowB = (uint32_t)(nb * 8 + (lane & 7)) * 128;
                    ldsm4(bb[q][0], bb[q][1], bb[q][2], bb[q][3],
                          sB + rowB + (((4u * t + bHi) ^ ls) << 4));
                }
                #pragma unroll
                for (int h = 0; h < 2; h++) {
                    #pragma unroll
                    for (int q = 0; q < 4; q++)
                        mma_tf32(acc[h][half * 4 + q], a[h][0], bb[q][0], bb[q][1]);
                    #pragma unroll
                    for (int q = 0; q < 4; q++)
                        mma_tf32(acc[h][half * 4 + q], a[h][1], bb[q][2], bb[q][3]);
                }
            }
        }
        __syncthreads();
        if (c0 + 2 < NCHUNK) issueStage(c0 + 2, s);
    }

    // ---- epilogue ----
    #pragma unroll
    for (int h = 0; h < 2; h++) {
        int r0 = wid * 32 + h * 16 + (lane >> 2);
        float bi0 = g_biasc[b * CH + r0];
        float bi1 = g_biasc[b * CH + r0 + 8];
        float* out0 = out + ((size_t)b * CH + r0) * HW;
        float* out1 = out0 + 8 * HW;
        #pragma unroll
        for (int nb = 0; nb < 8; nb++) {
            int p = p0 + nb * 8 + (lane & 3) * 2;
            *(float2*)(out0 + p) = make_float2(acc[h][nb][0] + bi0, acc[h][nb][1] + bi0);
            *(float2*)(out1 + p) = make_float2(acc[h][nb][2] + bi1, acc[h][nb][3] + bi1);
        }
    }
}

// ---------------------------------------------------------------------------
extern "C" void kernel_launch(void* const* d_in, const int* in_sizes, int n_in,
                              void* d_out, int out_size) {
    const float* x      = (const float*)d_in[0];
    const float* weight = (const float*)d_in[1];
    const float* bias   = (const float*)d_in[2];
    const float* gate_w = (const float*)d_in[3];
    const float* gate_b = (const float*)d_in[4];
    float* out = (float*)d_out;

    cudaFuncSetAttribute(conv_mma_kernel,
                         cudaFuncAttributeMaxDynamicSharedMemorySize, SMEM_BYTES);

    gap_kernel<<<BATCH * CH, 128>>>(x);
    gate_kernel<<<1, 256>>>(gate_w, gate_b, bias);
    combine_kernel<<<dim3(CH * KK2 / 4 / 256, BATCH), 256>>>(weight);
    xsplit_kernel<<<(int)((size_t)BATCH * CH * HW / 4 / 256), 256>>>(x);
    conv_mma_kernel<<<dim3(HW / BN, BATCH), 256, SMEM_BYTES>>>(out);
}

// round 12
// speedup vs baseline: 1.2777x; 1.2777x over previous
#include <cuda_runtime.h>
#include <cstdint>

#define BATCH 32
#define CH    256
#define HH    56
#define WW    56
#define HW    3136
#define KK2   2304      // CH*9
#define MEXP  8

#define BM 128          // o per CTA
#define BN 128          // pixels per CTA
#define BK 32           // k per chunk
#define NCHUNK (KK2 / BK)   // 72
#define NPIX_T ((HW + BN - 1) / BN)   // 25

// swizzled smem: row = 32 tf32 = 128B; 16B-group g stored at g ^ (row&7)
#define ATILE  (BM * 128)       // 16384
#define BTILE  (BN * 128)       // 16384
#define STAGE  (ATILE + BTILE)  // 32768
#define NSTAGE 3
#define SMEM_BYTES (NSTAGE * STAGE)   // 98304

// Scratch
__device__ float    g_gap[BATCH * CH];
__device__ float    g_alpha[BATCH * MEXP];
__device__ float    g_biasc[BATCH * CH];
__device__ uint32_t g_wt[(size_t)BATCH * CH * KK2];   // combined weights, tf32 [b][o][k]
__device__ uint32_t g_xt[(size_t)BATCH * CH * HW];    // x as tf32

// conv offset per kernel-position r: (r/3-1)*56 + (r%3-1)
__constant__ int c_doff[9] = { -57, -56, -55, -1, 0, 1, 55, 56, 57 };

// ---------------- helpers ----------------
__device__ __forceinline__ uint32_t smem_u32(const void* p) {
    uint32_t a;
    asm("{ .reg .u64 t; cvta.to.shared.u64 t, %1; cvt.u32.u64 %0, t; }" : "=r"(a) : "l"(p));
    return a;
}
__device__ __forceinline__ uint32_t f2tf32(float f) {
    uint32_t r; asm("cvt.rna.tf32.f32 %0, %1;" : "=r"(r) : "f"(f)); return r;
}
__device__ __forceinline__ void ldsm4(uint32_t& r0, uint32_t& r1, uint32_t& r2, uint32_t& r3,
                                      uint32_t addr) {
    asm volatile("ldmatrix.sync.aligned.m8n8.x4.shared.b16 {%0,%1,%2,%3}, [%4];"
                 : "=r"(r0), "=r"(r1), "=r"(r2), "=r"(r3) : "r"(addr));
}
__device__ __forceinline__ void mma_tf32(float* c, const uint32_t* a, uint32_t b0, uint32_t b1) {
    asm volatile(
        "mma.sync.aligned.m16n8k8.row.col.f32.tf32.tf32.f32 "
        "{%0,%1,%2,%3}, {%4,%5,%6,%7}, {%8,%9}, {%0,%1,%2,%3};"
        : "+f"(c[0]), "+f"(c[1]), "+f"(c[2]), "+f"(c[3])
        : "r"(a[0]), "r"(a[1]), "r"(a[2]), "r"(a[3]), "r"(b0), "r"(b1));
}
__device__ __forceinline__ void cpasync16(uint32_t dst, const void* src) {
    asm volatile("cp.async.cg.shared.global [%0], [%1], 16;" :: "r"(dst), "l"(src) : "memory");
}
__device__ __forceinline__ void cpasync4z(uint32_t dst, const void* src, uint32_t srcsz) {
    asm volatile("cp.async.ca.shared.global [%0], [%1], 4, %2;"
                 :: "r"(dst), "l"(src), "r"(srcsz) : "memory");
}

// ---------------------------------------------------------------------------
// 1) Global average pool
// ---------------------------------------------------------------------------
__global__ void gap_kernel(const float* __restrict__ x) {
    int bc = blockIdx.x;
    const float* p = x + (size_t)bc * HW;
    float s = 0.f;
    for (int i = threadIdx.x; i < HW; i += 128) s += p[i];
    __shared__ float sm[4];
    #pragma unroll
    for (int off = 16; off; off >>= 1) s += __shfl_down_sync(0xffffffffu, s, off);
    if ((threadIdx.x & 31) == 0) sm[threadIdx.x >> 5] = s;
    __syncthreads();
    if (threadIdx.x == 0)
        g_gap[bc] = (sm[0] + sm[1] + sm[2] + sm[3]) * (1.f / (float)HW);
}

// ---------------------------------------------------------------------------
// 2) Gate softmax + combined bias
// ---------------------------------------------------------------------------
__global__ void gate_kernel(const float* __restrict__ gate_w,
                            const float* __restrict__ gate_b,
                            const float* __restrict__ bias) {
    __shared__ float lg[BATCH][MEXP];
    __shared__ float al[BATCH][MEXP];
    int t = threadIdx.x;
    int b = t >> 3, m = t & 7;
    float acc = gate_b[m];
    const float* gp = &g_gap[b * CH];
    const float* gw = &gate_w[m * CH];
    for (int i = 0; i < CH; i++) acc += gp[i] * gw[i];
    lg[b][m] = acc;
    __syncthreads();
    if (t < BATCH) {
        float mx = lg[t][0];
        #pragma unroll
        for (int j = 1; j < MEXP; j++) mx = fmaxf(mx, lg[t][j]);
        float e[MEXP], s = 0.f;
        #pragma unroll
        for (int j = 0; j < MEXP; j++) { e[j] = expf(lg[t][j] - mx); s += e[j]; }
        float inv = 1.f / s;
        #pragma unroll
        for (int j = 0; j < MEXP; j++) { al[t][j] = e[j] * inv; g_alpha[t * MEXP + j] = e[j] * inv; }
    }
    __syncthreads();
    for (int b2 = 0; b2 < BATCH; b2++) {
        float s = 0.f;
        #pragma unroll
        for (int j = 0; j < MEXP; j++) s += al[b2][j] * bias[j * CH + t];
        g_biasc[b2 * CH + t] = s;
    }
}

// ---------------------------------------------------------------------------
// 3) Combine experts -> tf32
// ---------------------------------------------------------------------------
__global__ void combine_kernel(const float* __restrict__ weight) {
    int b = blockIdx.y;
    size_t i4 = (size_t)blockIdx.x * 256 + threadIdx.x;
    float a[MEXP];
    #pragma unroll
    for (int m = 0; m < MEXP; m++) a[m] = g_alpha[b * MEXP + m];
    float4 acc = make_float4(0.f, 0.f, 0.f, 0.f);
    #pragma unroll
    for (int m = 0; m < MEXP; m++) {
        const float4 v = ((const float4*)(weight + (size_t)m * CH * KK2))[i4];
        acc.x += a[m] * v.x; acc.y += a[m] * v.y;
        acc.z += a[m] * v.z; acc.w += a[m] * v.w;
    }
    uint4 o;
    o.x = f2tf32(acc.x); o.y = f2tf32(acc.y);
    o.z = f2tf32(acc.z); o.w = f2tf32(acc.w);
    ((uint4*)(g_wt + (size_t)b * CH * KK2))[i4] = o;
}

// ---------------------------------------------------------------------------
// 3b) x -> tf32
// ---------------------------------------------------------------------------
__global__ void xsplit_kernel(const float* __restrict__ x) {
    size_t i4 = (size_t)blockIdx.x * 256 + threadIdx.x;
    float4 v = ((const float4*)x)[i4];
    uint4 o;
    o.x = f2tf32(v.x); o.y = f2tf32(v.y);
    o.z = f2tf32(v.z); o.w = f2tf32(v.w);
    ((uint4*)g_xt)[i4] = o;
}

// ---------------------------------------------------------------------------
// 4) Conv GEMM: tf32 mma.sync m16n8k8. Tile 128(o) x 128(pix) x 32(k).
//    grid (25, 2, 32); 8 warps in 4(m) x 2(n), warp tile m32 x n64.
//    3-stage cp.async pipeline, 2 CTAs/SM.
// ---------------------------------------------------------------------------
__global__ void __launch_bounds__(256, 2)
conv_mma_kernel(float* __restrict__ out) {
    extern __shared__ char smem[];
    const uint32_t sbase = smem_u32(smem);
    const int tid  = threadIdx.x;
    const int wid  = tid >> 5;
    const int lane = tid & 31;
    const int warp_m = wid >> 1;       // 0..3
    const int warp_n = wid & 1;        // 0..1

    const int b  = blockIdx.z;
    const int o0 = blockIdx.y * BM;
    const int p0 = blockIdx.x * BN;

    // ---- A producer: thread -> (o-row ar, half seg): 4 x cp.async.16, swizzled
    const int ar  = tid >> 1;
    const int seg = tid & 1;
    const uint32_t* wRow = g_wt + ((size_t)(b * CH) + o0 + ar) * KK2 + seg * 16;
    const uint32_t ars = (uint32_t)(ar & 7);
    uint32_t aDstG[4];
    #pragma unroll
    for (int q = 0; q < 4; q++)
        aDstG[q] = (uint32_t)ar * 128 + (((uint32_t)(seg * 4 + q) ^ ars) << 4);

    // ---- B producer: thread -> pixel row pr = tid&127, k-half kh = tid>>7 (16 k's)
    const int pr = tid & 127;
    const int kh = tid >> 7;           // 0/1 -> k base 16*kh
    const int pp = p0 + pr;
    uint32_t vmask = 0;
    {
        int pc = (pp < HW) ? pp : 0;
        int hjv = pc / WW, wjv = pc - (pc / WW) * WW;
        if (pp < HW) {
            #pragma unroll
            for (int r = 0; r < 9; r++) {
                int ih = hjv + r / 3 - 1;
                int iw = wjv + r % 3 - 1;
                if ((unsigned)ih < HH && (unsigned)iw < WW) vmask |= (1u << r);
            }
        }
    }
    const int ppc = (pp < HW) ? pp : 0;
    // incremental state for k0 = kh*16
    int rst0, coff0;
    {
        int k0 = kh * 16;
        int c0 = k0 / 9;
        rst0  = k0 - 9 * c0;           // kh=0: 0 ; kh=1: 7
        coff0 = c0 * HW;
    }
    const uint32_t* xb = g_xt + (size_t)b * CH * HW;
    const uint32_t bRowDst = ATILE + (uint32_t)pr * 128;
    const uint32_t prs = (uint32_t)(pr & 7);

    // ---- consumer addresses
    const uint32_t ls  = (uint32_t)(lane & 7);
    const uint32_t aHi = (uint32_t)(lane >> 4);      // 0/1
    const uint32_t bHi = (uint32_t)(lane >> 3);      // 0..3
    const uint32_t aRow0 = (uint32_t)(warp_m * 32 + (lane & 15)) * 128;
    const uint32_t aRow1 = aRow0 + 16 * 128;

    float acc[2][8][4];
    #pragma unroll
    for (int h = 0; h < 2; h++)
        #pragma unroll
        for (int j = 0; j < 8; j++)
            #pragma unroll
            for (int q = 0; q < 4; q++) acc[h][j][q] = 0.f;

    auto issueStage = [&](int chunk, int s) {
        const uint32_t stg = sbase + s * STAGE;
        // A
        const uint32_t* srcA = wRow + chunk * BK;
        #pragma unroll
        for (int q = 0; q < 4; q++) cpasync16(stg + aDstG[q], srcA + q * 4);
        // B: 16 k-values for this thread's pixel
        int rr = rst0, cf = coff0;
        #pragma unroll
        for (int i = 0; i < 16; i++) {
            uint32_t ok = (vmask >> rr) & 1u;
            const uint32_t* src = ok ? (xb + cf + c_doff[rr] + ppc) : xb;
            int ki = kh * 16 + i;
            uint32_t dst = stg + bRowDst + (((uint32_t)(ki >> 2) ^ prs) << 4)
                         + (uint32_t)(ki & 3) * 4;
            cpasync4z(dst, src, ok ? 4u : 0u);
            rr++;
            if (rr == 9) { rr = 0; cf += HW; }
        }
        asm volatile("cp.async.commit_group;" ::: "memory");
        // advance by BK=32 k
        rst0 += 5;
        if (rst0 >= 9) { rst0 -= 9; coff0 += 4 * HW; }
        else coff0 += 3 * HW;
    };

    // ---- prologue ----
    issueStage(0, 0);
    issueStage(1, 1);

    int sIdx = 0;
    for (int c0 = 0; c0 < NCHUNK; c0++) {
        if (c0 + 2 < NCHUNK) {
            issueStage(c0 + 2, (sIdx + 2) % NSTAGE);
            asm volatile("cp.async.wait_group 2;" ::: "memory");
        } else if (c0 + 2 == NCHUNK) {
            asm volatile("cp.async.wait_group 1;" ::: "memory");
        } else {
            asm volatile("cp.async.wait_group 0;" ::: "memory");
        }
        __syncthreads();

        const uint32_t stg = sbase + sIdx * STAGE;
        const uint32_t sB  = stg + ATILE;

        #pragma unroll
        for (int t = 0; t < 2; t++) {
            uint32_t a[2][2][4];   // [m-half][k8 lo/hi]
            ldsm4(a[0][0][0], a[0][0][1], a[0][0][2], a[0][0][3],
                  stg + aRow0 + (((4u * t + 0 + aHi) ^ ls) << 4));
            ldsm4(a[0][1][0], a[0][1][1], a[0][1][2], a[0][1][3],
                  stg + aRow0 + (((4u * t + 2 + aHi) ^ ls) << 4));
            ldsm4(a[1][0][0], a[1][0][1], a[1][0][2], a[1][0][3],
                  stg + aRow1 + (((4u * t + 0 + aHi) ^ ls) << 4));
            ldsm4(a[1][1][0], a[1][1][1], a[1][1][2], a[1][1][3],
                  stg + aRow1 + (((4u * t + 2 + aHi) ^ ls) << 4));
            #pragma unroll
            for (int half = 0; half < 2; half++) {
                uint32_t bb[4][4];
                #pragma unroll
                for (int q = 0; q < 4; q++) {
                    int nb = warp_n * 8 + half * 4 + q;
                    uint32_t rowB = (uint32_t)(nb * 8 + (lane & 7)) * 128;
                    ldsm4(bb[q][0], bb[q][1], bb[q][2], bb[q][3],
                          sB + rowB + (((4u * t + bHi) ^ ls) << 4));
                }
                #pragma unroll
                for (int h = 0; h < 2; h++) {
                    #pragma unroll
                    for (int q = 0; q < 4; q++)
                        mma_tf32(acc[h][half * 4 + q], a[h][0], bb[q][0], bb[q][1]);
                    #pragma unroll
                    for (int q = 0; q < 4; q++)
                        mma_tf32(acc[h][half * 4 + q], a[h][1], bb[q][2], bb[q][3]);
                }
            }
        }
        __syncthreads();
        sIdx = (sIdx + 1) % NSTAGE;
    }

    // ---- epilogue ----
    #pragma unroll
    for (int h = 0; h < 2; h++) {
        int r0 = o0 + warp_m * 32 + h * 16 + (lane >> 2);
        float bi0 = g_biasc[b * CH + r0];
        float bi1 = g_biasc[b * CH + r0 + 8];
        float* out0 = out + ((size_t)b * CH + r0) * HW;
        float* out1 = out0 + 8 * HW;
        #pragma unroll
        for (int nb = 0; nb < 8; nb++) {
            int p = p0 + warp_n * 64 + nb * 8 + (lane & 3) * 2;
            if (p < HW) {
                *(float2*)(out0 + p) = make_float2(acc[h][nb][0] + bi0, acc[h][nb][1] + bi0);
                *(float2*)(out1 + p) = make_float2(acc[h][nb][2] + bi1, acc[h][nb][3] + bi1);
            }
        }
    }
}

// ---------------------------------------------------------------------------
extern "C" void kernel_launch(void* const* d_in, const int* in_sizes, int n_in,
                              void* d_out, int out_size) {
    const float* x      = (const float*)d_in[0];
    const float* weight = (const float*)d_in[1];
    const float* bias   = (const float*)d_in[2];
    const float* gate_w = (const float*)d_in[3];
    const float* gate_b = (const float*)d_in[4];
    float* out = (float*)d_out;

    cudaFuncSetAttribute(conv_mma_kernel,
                         cudaFuncAttributeMaxDynamicSharedMemorySize, SMEM_BYTES);

    gap_kernel<<<BATCH * CH, 128>>>(x);
    gate_kernel<<<1, 256>>>(gate_w, gate_b, bias);
    combine_kernel<<<dim3(CH * KK2 / 4 / 256, BATCH), 256>>>(weight);
    xsplit_kernel<<<(int)((size_t)BATCH * CH * HW / 4 / 256), 256>>>(x);
    conv_mma_kernel<<<dim3(NPIX_T, CH / BM, BATCH), 256, SMEM_BYTES>>>(out);
}

// round 13
// speedup vs baseline: 1.5696x; 1.2285x over previous
#include <cuda_runtime.h>
#include <cstdint>

#define BATCH 32
#define CH    256
#define HH    56
#define WW    56
#define HW    3136
#define KK2   2304      // CH*9
#define MEXP  8

#define BM 128
#define BN 128
#define BK 32
#define NCHUNK (KK2 / BK)          // 72
#define NPIX_T ((HW + BN - 1) / BN) // 25

// padded x: per (dw-plane, b*CH+c): 58 rows x 64 cols tf32
#define XROW   64
#define XCH    (58 * XROW)          // 3712
#define XPLANE (BATCH * CH * XCH)   // 30408704

// smem: A = 128 rows x 128B (XOR swizzle). B = 32 k-rows x 544B (128 pixels + pad).
#define ATILE  (BM * 128)           // 16384
#define BROWB  544
#define BTILE  (BK * BROWB)         // 17408
#define STAGE  (ATILE + BTILE)      // 33792
#define NSTAGE 3
#define SMEM_BYTES (NSTAGE * STAGE) // 101376

// Scratch
__device__ float    g_gap[BATCH * CH];
__device__ float    g_alpha[BATCH * MEXP];
__device__ float    g_biasc[BATCH * CH];
__device__ uint32_t g_wt[(size_t)BATCH * CH * KK2];       // combined weights tf32 [b][o][k]
__device__ uint32_t g_xp[(size_t)3 * XPLANE + 4096];      // padded shifted x planes (+guard)

// per kernel-position r (= 3*(dh+1) + (dw+1)): plane + dh row offset (element units)
__constant__ int c_rtab[9] = {
    -XROW,              XPLANE - XROW,       2 * XPLANE - XROW,
    0,                  XPLANE,              2 * XPLANE,
    XROW,               XPLANE + XROW,       2 * XPLANE + XROW
};

// ---------------- helpers ----------------
__device__ __forceinline__ uint32_t smem_u32(const void* p) {
    uint32_t a;
    asm("{ .reg .u64 t; cvta.to.shared.u64 t, %1; cvt.u32.u64 %0, t; }" : "=r"(a) : "l"(p));
    return a;
}
__device__ __forceinline__ uint32_t f2tf32(float f) {
    uint32_t r; asm("cvt.rna.tf32.f32 %0, %1;" : "=r"(r) : "f"(f)); return r;
}
__device__ __forceinline__ void ldsm4(uint32_t& r0, uint32_t& r1, uint32_t& r2, uint32_t& r3,
                                      uint32_t addr) {
    asm volatile("ldmatrix.sync.aligned.m8n8.x4.shared.b16 {%0,%1,%2,%3}, [%4];"
                 : "=r"(r0), "=r"(r1), "=r"(r2), "=r"(r3) : "r"(addr));
}
__device__ __forceinline__ uint32_t lds32(uint32_t addr) {
    uint32_t v;
    asm volatile("ld.shared.b32 %0, [%1];" : "=r"(v) : "r"(addr));
    return v;
}
__device__ __forceinline__ void mma_tf32(float* c, const uint32_t* a, uint32_t b0, uint32_t b1) {
    asm volatile(
        "mma.sync.aligned.m16n8k8.row.col.f32.tf32.tf32.f32 "
        "{%0,%1,%2,%3}, {%4,%5,%6,%7}, {%8,%9}, {%0,%1,%2,%3};"
        : "+f"(c[0]), "+f"(c[1]), "+f"(c[2]), "+f"(c[3])
        : "r"(a[0]), "r"(a[1]), "r"(a[2]), "r"(a[3]), "r"(b0), "r"(b1));
}
__device__ __forceinline__ void cpasync16(uint32_t dst, const void* src) {
    asm volatile("cp.async.cg.shared.global [%0], [%1], 16;" :: "r"(dst), "l"(src) : "memory");
}

// ---------------------------------------------------------------------------
// 1) Global average pool
// ---------------------------------------------------------------------------
__global__ void gap_kernel(const float* __restrict__ x) {
    int bc = blockIdx.x;
    const float* p = x + (size_t)bc * HW;
    float s = 0.f;
    for (int i = threadIdx.x; i < HW; i += 128) s += p[i];
    __shared__ float sm[4];
    #pragma unroll
    for (int off = 16; off; off >>= 1) s += __shfl_down_sync(0xffffffffu, s, off);
    if ((threadIdx.x & 31) == 0) sm[threadIdx.x >> 5] = s;
    __syncthreads();
    if (threadIdx.x == 0)
        g_gap[bc] = (sm[0] + sm[1] + sm[2] + sm[3]) * (1.f / (float)HW);
}

// ---------------------------------------------------------------------------
// 2) Gate softmax + combined bias
// ---------------------------------------------------------------------------
__global__ void gate_kernel(const float* __restrict__ gate_w,
                            const float* __restrict__ gate_b,
                            const float* __restrict__ bias) {
    __shared__ float lg[BATCH][MEXP];
    __shared__ float al[BATCH][MEXP];
    int t = threadIdx.x;
    int b = t >> 3, m = t & 7;
    float acc = gate_b[m];
    const float* gp = &g_gap[b * CH];
    const float* gw = &gate_w[m * CH];
    for (int i = 0; i < CH; i++) acc += gp[i] * gw[i];
    lg[b][m] = acc;
    __syncthreads();
    if (t < BATCH) {
        float mx = lg[t][0];
        #pragma unroll
        for (int j = 1; j < MEXP; j++) mx = fmaxf(mx, lg[t][j]);
        float e[MEXP], s = 0.f;
        #pragma unroll
        for (int j = 0; j < MEXP; j++) { e[j] = expf(lg[t][j] - mx); s += e[j]; }
        float inv = 1.f / s;
        #pragma unroll
        for (int j = 0; j < MEXP; j++) { al[t][j] = e[j] * inv; g_alpha[t * MEXP + j] = e[j] * inv; }
    }
    __syncthreads();
    for (int b2 = 0; b2 < BATCH; b2++) {
        float s = 0.f;
        #pragma unroll
        for (int j = 0; j < MEXP; j++) s += al[b2][j] * bias[j * CH + t];
        g_biasc[b2 * CH + t] = s;
    }
}

// ---------------------------------------------------------------------------
// 3) Combine experts -> tf32
// ---------------------------------------------------------------------------
__global__ void combine_kernel(const float* __restrict__ weight) {
    int b = blockIdx.y;
    size_t i4 = (size_t)blockIdx.x * 256 + threadIdx.x;
    float a[MEXP];
    #pragma unroll
    for (int m = 0; m < MEXP; m++) a[m] = g_alpha[b * MEXP + m];
    float4 acc = make_float4(0.f, 0.f, 0.f, 0.f);
    #pragma unroll
    for (int m = 0; m < MEXP; m++) {
        const float4 v = ((const float4*)(weight + (size_t)m * CH * KK2))[i4];
        acc.x += a[m] * v.x; acc.y += a[m] * v.y;
        acc.z += a[m] * v.z; acc.w += a[m] * v.w;
    }
    uint4 o;
    o.x = f2tf32(acc.x); o.y = f2tf32(acc.y);
    o.z = f2tf32(acc.z); o.w = f2tf32(acc.w);
    ((uint4*)(g_wt + (size_t)b * CH * KK2))[i4] = o;
}

// ---------------------------------------------------------------------------
// 3b) Build padded, shifted tf32 x planes: plane dwsel holds x(h, w+dwsel-1)
//     at [bc][h+1][w]; zero borders/shift-outs. grid (8192, 3), 256 thr.
// ---------------------------------------------------------------------------
__global__ void xpad_kernel(const float* __restrict__ x) {
    int bc    = blockIdx.x;
    int dwsel = blockIdx.y;
    int dw    = dwsel - 1;
    const float* xc = x + (size_t)bc * HW;
    uint32_t* dst = g_xp + (size_t)dwsel * XPLANE + (size_t)bc * XCH;
    for (int i = threadIdx.x; i < XCH; i += 256) {
        int row = i >> 6, w = i & 63;
        int h = row - 1, ws = w + dw;
        float v = 0.f;
        if ((unsigned)h < HH && w < WW && (unsigned)ws < WW) v = xc[h * WW + ws];
        dst[i] = f2tf32(v);
    }
}

// ---------------------------------------------------------------------------
// 4) Conv GEMM: tf32 mma.sync m16n8k8. Tile 128(o) x 128(pix) x 32(k).
//    grid (25, 2, 32); 8 warps 4(m) x 2(n), warp m32 x n64.
//    3-stage cp.async pipeline; all-16B aligned unconditional gathers.
// ---------------------------------------------------------------------------
__global__ void __launch_bounds__(256, 2)
conv_mma_kernel(float* __restrict__ out) {
    extern __shared__ char smem[];
    const uint32_t sbase = smem_u32(smem);
    const int tid  = threadIdx.x;
    const int wid  = tid >> 5;
    const int lane = tid & 31;
    const int warp_m = wid >> 1;
    const int warp_n = wid & 1;

    const int b  = blockIdx.z;
    const int o0 = blockIdx.y * BM;
    const int p0 = blockIdx.x * BN;
    const int bc0 = b * CH;

    // ---- A producer: instr q covers rows q*32 + wid*4 + (lane>>3), group lane&7
    const int aRowIn = lane >> 3;
    const int ag     = lane & 7;
    uint32_t aDst[4];
    const uint32_t* aSrc[4];
    #pragma unroll
    for (int q = 0; q < 4; q++) {
        int row = q * 32 + wid * 4 + aRowIn;
        aDst[q] = (uint32_t)row * 128 + (((uint32_t)(ag ^ (row & 7))) << 4);
        aSrc[q] = g_wt + ((size_t)(bc0 + o0 + row)) * KK2 + ag * 4;
    }

    // ---- B producer: warp covers k-rows wid*4..+3; lane -> 4 pixels p0+lane*4..
    int pB = p0 + lane * 4;
    int hB = pB / WW;
    const int pixoff = (hB + 1) * XROW + (pB - hB * WW);
    int rj[4], cj[4];
    #pragma unroll
    for (int j = 0; j < 4; j++) {
        int k0 = wid * 4 + j;
        cj[j] = k0 / 9;
        rj[j] = k0 - 9 * cj[j];
    }
    const uint32_t* xpb = g_xp + (size_t)bc0 * XCH;
    uint32_t bDst[4];
    #pragma unroll
    for (int j = 0; j < 4; j++)
        bDst[j] = ATILE + (uint32_t)(wid * 4 + j) * BROWB + (uint32_t)lane * 16;

    // ---- consumer addresses
    const uint32_t ls  = (uint32_t)(lane & 7);
    const uint32_t aHi = (uint32_t)(lane >> 4);
    const uint32_t aRow0 = (uint32_t)(warp_m * 32 + (lane & 15)) * 128;
    const uint32_t aRow1 = aRow0 + 16 * 128;
    // B fragment lane base: k-row = lane&3, n-col = warp_n*64 + lane>>2
    const uint32_t bLane = ATILE + (uint32_t)(lane & 3) * BROWB
                         + (uint32_t)(warp_n * 64 + (lane >> 2)) * 4;

    float acc[2][8][4];
    #pragma unroll
    for (int h = 0; h < 2; h++)
        #pragma unroll
        for (int j = 0; j < 8; j++)
            #pragma unroll
            for (int q = 0; q < 4; q++) acc[h][j][q] = 0.f;

    auto issueStage = [&](int chunk, int s) {
        const uint32_t stg = sbase + s * STAGE;
        #pragma unroll
        for (int q = 0; q < 4; q++) cpasync16(stg + aDst[q], aSrc[q] + chunk * BK);
        #pragma unroll
        for (int j = 0; j < 4; j++) {
            const uint32_t* src = xpb + cj[j] * XCH + c_rtab[rj[j]] + pixoff;
            cpasync16(stg + bDst[j], src);
            rj[j] += 5;
            if (rj[j] >= 9) { rj[j] -= 9; cj[j] += 4; }
            else cj[j] += 3;
        }
        asm volatile("cp.async.commit_group;" ::: "memory");
    };

    // ---- prologue ----
    issueStage(0, 0);
    issueStage(1, 1);

    int sIdx = 0;
    for (int c0 = 0; c0 < NCHUNK; c0++) {
        if (c0 + 2 < NCHUNK) {
            issueStage(c0 + 2, (sIdx + 2) % NSTAGE);
            asm volatile("cp.async.wait_group 2;" ::: "memory");
        } else if (c0 + 2 == NCHUNK) {
            asm volatile("cp.async.wait_group 1;" ::: "memory");
        } else {
            asm volatile("cp.async.wait_group 0;" ::: "memory");
        }
        __syncthreads();

        const uint32_t stg = sbase + sIdx * STAGE;

        #pragma unroll
        for (int t = 0; t < 2; t++) {
            uint32_t a[2][2][4];
            ldsm4(a[0][0][0], a[0][0][1], a[0][0][2], a[0][0][3],
                  stg + aRow0 + (((4u * t + 0 + aHi) ^ ls) << 4));
            ldsm4(a[0][1][0], a[0][1][1], a[0][1][2], a[0][1][3],
                  stg + aRow0 + (((4u * t + 2 + aHi) ^ ls) << 4));
            ldsm4(a[1][0][0], a[1][0][1], a[1][0][2], a[1][0][3],
                  stg + aRow1 + (((4u * t + 0 + aHi) ^ ls) << 4));
            ldsm4(a[1][1][0], a[1][1][1], a[1][1][2], a[1][1][3],
                  stg + aRow1 + (((4u * t + 2 + aHi) ^ ls) << 4));
            const uint32_t bT = stg + bLane + (uint32_t)t * (16 * BROWB);
            #pragma unroll
            for (int half = 0; half < 2; half++) {
                uint32_t bb[4][4];
                #pragma unroll
                for (int q = 0; q < 4; q++) {
                    uint32_t a0 = bT + (uint32_t)(half * 4 + q) * 32;
                    bb[q][0] = lds32(a0);
                    bb[q][1] = lds32(a0 + 4 * BROWB);
                    bb[q][2] = lds32(a0 + 8 * BROWB);
                    bb[q][3] = lds32(a0 + 12 * BROWB);
                }
                #pragma unroll
                for (int h = 0; h < 2; h++) {
                    #pragma unroll
                    for (int q = 0; q < 4; q++)
                        mma_tf32(acc[h][half * 4 + q], a[h][0], bb[q][0], bb[q][1]);
                    #pragma unroll
                    for (int q = 0; q < 4; q++)
                        mma_tf32(acc[h][half * 4 + q], a[h][1], bb[q][2], bb[q][3]);
                }
            }
        }
        __syncthreads();
        sIdx = (sIdx + 1) % NSTAGE;
    }

    // ---- epilogue ----
    #pragma unroll
    for (int h = 0; h < 2; h++) {
        int r0 = o0 + warp_m * 32 + h * 16 + (lane >> 2);
        float bi0 = g_biasc[b * CH + r0];
        float bi1 = g_biasc[b * CH + r0 + 8];
        float* out0 = out + ((size_t)b * CH + r0) * HW;
        float* out1 = out0 + 8 * HW;
        #pragma unroll
        for (int nb = 0; nb < 8; nb++) {
            int p = p0 + warp_n * 64 + nb * 8 + (lane & 3) * 2;
            if (p < HW) {
                *(float2*)(out0 + p) = make_float2(acc[h][nb][0] + bi0, acc[h][nb][1] + bi0);
                *(float2*)(out1 + p) = make_float2(acc[h][nb][2] + bi1, acc[h][nb][3] + bi1);
            }
        }
    }
}

// ---------------------------------------------------------------------------
extern "C" void kernel_launch(void* const* d_in, const int* in_sizes, int n_in,
                              void* d_out, int out_size) {
    const float* x      = (const float*)d_in[0];
    const float* weight = (const float*)d_in[1];
    const float* bias   = (const float*)d_in[2];
    const float* gate_w = (const float*)d_in[3];
    const float* gate_b = (const float*)d_in[4];
    float* out = (float*)d_out;

    cudaFuncSetAttribute(conv_mma_kernel,
                         cudaFuncAttributeMaxDynamicSharedMemorySize, SMEM_BYTES);

    gap_kernel<<<BATCH * CH, 128>>>(x);
    gate_kernel<<<1, 256>>>(gate_w, gate_b, bias);
    combine_kernel<<<dim3(CH * KK2 / 4 / 256, BATCH), 256>>>(weight);
    xpad_kernel<<<dim3(BATCH * CH, 3), 256>>>(x);
    conv_mma_kernel<<<dim3(NPIX_T, CH / BM, BATCH), 256, SMEM_BYTES>>>(out);
}

// round 15
// speedup vs baseline: 1.7851x; 1.1373x over previous
#include <cuda_runtime.h>
#include <cstdint>

#define BATCH 32
#define CH    256
#define HH    56
#define WW    56
#define HW    3136
#define KK2   2304      // CH*9
#define MEXP  8

#define BM 128
#define BN 128
#define BK 32
#define NCHUNK (KK2 / BK)          // 72
#define NPIX_T ((HW + BN - 1) / BN) // 25

// padded x: per (dw-plane, b*CH+c): 58 rows x 64 cols tf32
#define XROW   64
#define XCH    (58 * XROW)          // 3712
#define XPLANE (BATCH * CH * XCH)   // 30408704

// smem: A = 128 rows x 128B (XOR swizzle). B = 32 k-rows x 544B (128 pixels + pad).
#define ATILE  (BM * 128)           // 16384
#define BROWB  544
#define BTILE  (BK * BROWB)         // 17408
#define STAGE  (ATILE + BTILE)      // 33792
#define NSTAGE 3
#define SMEM_BYTES (NSTAGE * STAGE) // 101376

// Scratch
__device__ float    g_gap[BATCH * CH];
__device__ float    g_alpha[BATCH * MEXP];
__device__ float    g_biasc[BATCH * CH];
__device__ uint32_t g_wt[(size_t)BATCH * CH * KK2];       // combined weights tf32 [b][o][k]
__device__ uint32_t g_xp[(size_t)3 * XPLANE + 4096];      // padded shifted x planes (+guard)

// per kernel-position r (= 3*(dh+1) + (dw+1)): plane + dh row offset (element units)
__constant__ int c_rtab[9] = {
    -XROW,              XPLANE - XROW,       2 * XPLANE - XROW,
    0,                  XPLANE,              2 * XPLANE,
    XROW,               XPLANE + XROW,       2 * XPLANE + XROW
};

// ---------------- helpers ----------------
__device__ __forceinline__ uint32_t smem_u32(const void* p) {
    uint32_t a;
    asm("{ .reg .u64 t; cvta.to.shared.u64 t, %1; cvt.u32.u64 %0, t; }" : "=r"(a) : "l"(p));
    return a;
}
__device__ __forceinline__ uint32_t f2tf32(float f) {
    uint32_t r; asm("cvt.rna.tf32.f32 %0, %1;" : "=r"(r) : "f"(f)); return r;
}
__device__ __forceinline__ void ldsm4(uint32_t& r0, uint32_t& r1, uint32_t& r2, uint32_t& r3,
                                      uint32_t addr) {
    asm volatile("ldmatrix.sync.aligned.m8n8.x4.shared.b16 {%0,%1,%2,%3}, [%4];"
                 : "=r"(r0), "=r"(r1), "=r"(r2), "=r"(r3) : "r"(addr));
}
__device__ __forceinline__ uint32_t lds32(uint32_t addr) {
    uint32_t v;
    asm volatile("ld.shared.b32 %0, [%1];" : "=r"(v) : "r"(addr));
    return v;
}
__device__ __forceinline__ void mma_tf32(float* c, const uint32_t* a, uint32_t b0, uint32_t b1) {
    asm volatile(
        "mma.sync.aligned.m16n8k8.row.col.f32.tf32.tf32.f32 "
        "{%0,%1,%2,%3}, {%4,%5,%6,%7}, {%8,%9}, {%0,%1,%2,%3};"
        : "+f"(c[0]), "+f"(c[1]), "+f"(c[2]), "+f"(c[3])
        : "r"(a[0]), "r"(a[1]), "r"(a[2]), "r"(a[3]), "r"(b0), "r"(b1));
}
__device__ __forceinline__ void cpasync16(uint32_t dst, const void* src) {
    asm volatile("cp.async.cg.shared.global [%0], [%1], 16;" :: "r"(dst), "l"(src) : "memory");
}

// ---------------------------------------------------------------------------
// 1) Global average pool
// ---------------------------------------------------------------------------
__global__ void gap_kernel(const float* __restrict__ x) {
    int bc = blockIdx.x;
    const float* p = x + (size_t)bc * HW;
    float s = 0.f;
    for (int i = threadIdx.x; i < HW; i += 128) s += p[i];
    __shared__ float sm[4];
    #pragma unroll
    for (int off = 16; off; off >>= 1) s += __shfl_down_sync(0xffffffffu, s, off);
    if ((threadIdx.x & 31) == 0) sm[threadIdx.x >> 5] = s;
    __syncthreads();
    if (threadIdx.x == 0)
        g_gap[bc] = (sm[0] + sm[1] + sm[2] + sm[3]) * (1.f / (float)HW);
}

// ---------------------------------------------------------------------------
// 2) Gate softmax + combined bias
// ---------------------------------------------------------------------------
__global__ void gate_kernel(const float* __restrict__ gate_w,
                            const float* __restrict__ gate_b,
                            const float* __restrict__ bias) {
    __shared__ float lg[BATCH][MEXP];
    __shared__ float al[BATCH][MEXP];
    int t = threadIdx.x;
    int b = t >> 3, m = t & 7;
    float acc = gate_b[m];
    const float* gp = &g_gap[b * CH];
    const float* gw = &gate_w[m * CH];
    for (int i = 0; i < CH; i++) acc += gp[i] * gw[i];
    lg[b][m] = acc;
    __syncthreads();
    if (t < BATCH) {
        float mx = lg[t][0];
        #pragma unroll
        for (int j = 1; j < MEXP; j++) mx = fmaxf(mx, lg[t][j]);
        float e[MEXP], s = 0.f;
        #pragma unroll
        for (int j = 0; j < MEXP; j++) { e[j] = expf(lg[t][j] - mx); s += e[j]; }
        float inv = 1.f / s;
        #pragma unroll
        for (int j = 0; j < MEXP; j++) { al[t][j] = e[j] * inv; g_alpha[t * MEXP + j] = e[j] * inv; }
    }
    __syncthreads();
    for (int b2 = 0; b2 < BATCH; b2++) {
        float s = 0.f;
        #pragma unroll
        for (int j = 0; j < MEXP; j++) s += al[b2][j] * bias[j * CH + t];
        g_biasc[b2 * CH + t] = s;
    }
}

// ---------------------------------------------------------------------------
// 3) Combine experts -> tf32
// ---------------------------------------------------------------------------
__global__ void combine_kernel(const float* __restrict__ weight) {
    int b = blockIdx.y;
    size_t i4 = (size_t)blockIdx.x * 256 + threadIdx.x;
    float a[MEXP];
    #pragma unroll
    for (int m = 0; m < MEXP; m++) a[m] = g_alpha[b * MEXP + m];
    float4 acc = make_float4(0.f, 0.f, 0.f, 0.f);
    #pragma unroll
    for (int m = 0; m < MEXP; m++) {
        const float4 v = ((const float4*)(weight + (size_t)m * CH * KK2))[i4];
        acc.x += a[m] * v.x; acc.y += a[m] * v.y;
        acc.z += a[m] * v.z; acc.w += a[m] * v.w;
    }
    uint4 o;
    o.x = f2tf32(acc.x); o.y = f2tf32(acc.y);
    o.z = f2tf32(acc.z); o.w = f2tf32(acc.w);
    ((uint4*)(g_wt + (size_t)b * CH * KK2))[i4] = o;
}

// ---------------------------------------------------------------------------
// 3b) Padded shifted tf32 x planes, vectorized: 1 uint4 store per iteration.
//     grid (8192, 3), 256 threads; 58*16 = 928 uint4 per (bc, plane).
// ---------------------------------------------------------------------------
__global__ void xpad_kernel(const float* __restrict__ x) {
    int bc    = blockIdx.x;
    int dwsel = blockIdx.y;
    int dw    = dwsel - 1;
    const float* xc = x + (size_t)bc * HW;
    uint4* dst = (uint4*)(g_xp + (size_t)dwsel * XPLANE + (size_t)bc * XCH);
    #pragma unroll 4
    for (int i4 = threadIdx.x; i4 < 58 * 16; i4 += 256) {
        int row = i4 >> 4;
        int wq  = (i4 & 15) * 4;
        int h   = row - 1;
        bool rv = (unsigned)h < HH;
        const float* xr = xc + h * WW + dw;
        uint4 o;
        {
            int w = wq;     int ws = w + dw;
            o.x = (rv && (unsigned)ws < WW && w < WW) ? f2tf32(xr[w]) : 0u;
            w = wq + 1;     ws = w + dw;
            o.y = (rv && (unsigned)ws < WW && w < WW) ? f2tf32(xr[w]) : 0u;
            w = wq + 2;     ws = w + dw;
            o.z = (rv && (unsigned)ws < WW && w < WW) ? f2tf32(xr[w]) : 0u;
            w = wq + 3;     ws = w + dw;
            o.w = (rv && (unsigned)ws < WW && w < WW) ? f2tf32(xr[w]) : 0u;
        }
        dst[i4] = o;
    }
}

// ---------------------------------------------------------------------------
// 4) Conv GEMM: tf32 mma.sync m16n8k8. Tile 128(o) x 128(pix) x 32(k).
//    grid (25, 2, 32); 8 warps 4(m) x 2(n), warp m32 x n64.
//    3-stage cp.async pipeline, ONE barrier per chunk.
// ---------------------------------------------------------------------------
__global__ void __launch_bounds__(256, 2)
conv_mma_kernel(float* __restrict__ out) {
    extern __shared__ char smem[];
    const uint32_t sbase = smem_u32(smem);
    const int tid  = threadIdx.x;
    const int wid  = tid >> 5;
    const int lane = tid & 31;
    const int warp_m = wid >> 1;
    const int warp_n = wid & 1;

    const int b  = blockIdx.z;
    const int o0 = blockIdx.y * BM;
    const int p0 = blockIdx.x * BN;
    const int bc0 = b * CH;

    // ---- A producer: instr q covers rows q*32 + wid*4 + (lane>>3), group lane&7
    const int aRowIn = lane >> 3;
    const int ag     = lane & 7;
    uint32_t aDst[4];
    const uint32_t* aSrc[4];
    #pragma unroll
    for (int q = 0; q < 4; q++) {
        int row = q * 32 + wid * 4 + aRowIn;
        aDst[q] = (uint32_t)row * 128 + (((uint32_t)(ag ^ (row & 7))) << 4);
        aSrc[q] = g_wt + ((size_t)(bc0 + o0 + row)) * KK2 + ag * 4;
    }

    // ---- B producer: warp covers k-rows wid*4..+3; lane -> 4 pixels p0+lane*4..
    int pB = p0 + lane * 4;
    int hB = pB / WW;
    const int pixoff = (hB + 1) * XROW + (pB - hB * WW);
    int rj[4], cj[4];
    #pragma unroll
    for (int j = 0; j < 4; j++) {
        int k0 = wid * 4 + j;
        cj[j] = k0 / 9;
        rj[j] = k0 - 9 * cj[j];
    }
    const uint32_t* xpb = g_xp + (size_t)bc0 * XCH;
    uint32_t bDst[4];
    #pragma unroll
    for (int j = 0; j < 4; j++)
        bDst[j] = ATILE + (uint32_t)(wid * 4 + j) * BROWB + (uint32_t)lane * 16;

    // ---- consumer addresses
    const uint32_t ls  = (uint32_t)(lane & 7);
    const uint32_t aHi = (uint32_t)(lane >> 4);
    const uint32_t aRow0 = (uint32_t)(warp_m * 32 + (lane & 15)) * 128;
    const uint32_t aRow1 = aRow0 + 16 * 128;
    const uint32_t bLane = ATILE + (uint32_t)(lane & 3) * BROWB
                         + (uint32_t)(warp_n * 64 + (lane >> 2)) * 4;

    float acc[2][8][4];
    #pragma unroll
    for (int h = 0; h < 2; h++)
        #pragma unroll
        for (int j = 0; j < 8; j++)
            #pragma unroll
            for (int q = 0; q < 4; q++) acc[h][j][q] = 0.f;

    auto issueStage = [&](int chunk, int s) {
        const uint32_t stg = sbase + s * STAGE;
        #pragma unroll
        for (int q = 0; q < 4; q++) cpasync16(stg + aDst[q], aSrc[q] + chunk * BK);
        #pragma unroll
        for (int j = 0; j < 4; j++) {
            const uint32_t* src = xpb + cj[j] * XCH + c_rtab[rj[j]] + pixoff;
            cpasync16(stg + bDst[j], src);
            rj[j] += 5;
            if (rj[j] >= 9) { rj[j] -= 9; cj[j] += 4; }
            else cj[j] += 3;
        }
        asm volatile("cp.async.commit_group;" ::: "memory");
    };

    // ---- prologue ----
    issueStage(0, 0);
    issueStage(1, 1);

    int sIdx = 0;
    for (int c0 = 0; c0 < NCHUNK; c0++) {
        if (c0 + 1 < NCHUNK)
            asm volatile("cp.async.wait_group 1;" ::: "memory");
        else
            asm volatile("cp.async.wait_group 0;" ::: "memory");
        __syncthreads();
        // safe: all readers of stage (sIdx+2)%3 (= iteration c0-1's stage) passed the barrier
        if (c0 + 2 < NCHUNK) issueStage(c0 + 2, (sIdx + 2) % NSTAGE);

        const uint32_t stg = sbase + sIdx * STAGE;

        #pragma unroll
        for (int t = 0; t < 2; t++) {
            uint32_t a[2][2][4];
            ldsm4(a[0][0][0], a[0][0][1], a[0][0][2], a[0][0][3],
                  stg + aRow0 + (((4u * t + 0 + aHi) ^ ls) << 4));
            ldsm4(a[0][1][0], a[0][1][1], a[0][1][2], a[0][1][3],
                  stg + aRow0 + (((4u * t + 2 + aHi) ^ ls) << 4));
            ldsm4(a[1][0][0], a[1][0][1], a[1][0][2], a[1][0][3],
                  stg + aRow1 + (((4u * t + 0 + aHi) ^ ls) << 4));
            ldsm4(a[1][1][0], a[1][1][1], a[1][1][2], a[1][1][3],
                  stg + aRow1 + (((4u * t + 2 + aHi) ^ ls) << 4));
            const uint32_t bT = stg + bLane + (uint32_t)t * (16 * BROWB);
            #pragma unroll
            for (int half = 0; half < 2; half++) {
                uint32_t bb[4][4];
                #pragma unroll
                for (int q = 0; q < 4; q++) {
                    uint32_t a0 = bT + (uint32_t)(half * 4 + q) * 32;
                    bb[q][0] = lds32(a0);
                    bb[q][1] = lds32(a0 + 4 * BROWB);
                    bb[q][2] = lds32(a0 + 8 * BROWB);
                    bb[q][3] = lds32(a0 + 12 * BROWB);
                }
                #pragma unroll
                for (int h = 0; h < 2; h++) {
                    #pragma unroll
                    for (int q = 0; q < 4; q++)
                        mma_tf32(acc[h][half * 4 + q], a[h][0], bb[q][0], bb[q][1]);
                    #pragma unroll
                    for (int q = 0; q < 4; q++)
                        mma_tf32(acc[h][half * 4 + q], a[h][1], bb[q][2], bb[q][3]);
                }
            }
        }
        sIdx = (sIdx + 1) % NSTAGE;
    }

    // ---- epilogue ----
    #pragma unroll
    for (int h = 0; h < 2; h++) {
        int r0 = o0 + warp_m * 32 + h * 16 + (lane >> 2);
        float bi0 = g_biasc[b * CH + r0];
        float bi1 = g_biasc[b * CH + r0 + 8];
        float* out0 = out + ((size_t)b * CH + r0) * HW;
        float* out1 = out0 + 8 * HW;
        #pragma unroll
        for (int nb = 0; nb < 8; nb++) {
            int p = p0 + warp_n * 64 + nb * 8 + (lane & 3) * 2;
            if (p < HW) {
                *(float2*)(out0 + p) = make_float2(acc[h][nb][0] + bi0, acc[h][nb][1] + bi0);
                *(float2*)(out1 + p) = make_float2(acc[h][nb][2] + bi1, acc[h][nb][3] + bi1);
            }
        }
    }
}

// ---------------------------------------------------------------------------
extern "C" void kernel_launch(void* const* d_in, const int* in_sizes, int n_in,
                              void* d_out, int out_size) {
    const float* x      = (const float*)d_in[0];
    const float* weight = (const float*)d_in[1];
    const float* bias   = (const float*)d_in[2];
    const float* gate_w = (const float*)d_in[3];
    const float* gate_b = (const float*)d_in[4];
    float* out = (float*)d_out;

    cudaFuncSetAttribute(conv_mma_kernel,
                         cudaFuncAttributeMaxDynamicSharedMemorySize, SMEM_BYTES);

    gap_kernel<<<BATCH * CH, 128>>>(x);
    gate_kernel<<<1, 256>>>(gate_w, gate_b, bias);
    combine_kernel<<<dim3(CH * KK2 / 4 / 256, BATCH), 256>>>(weight);
    xpad_kernel<<<dim3(BATCH * CH, 3), 256>>>(x);
    conv_mma_kernel<<<dim3(NPIX_T, CH / BM, BATCH), 256, SMEM_BYTES>>>(out);
}

// round 17
// speedup vs baseline: 1.9673x; 1.1021x over previous
#include <cuda_runtime.h>
#include <cstdint>

#define BATCH 32
#define CH    256
#define HH    56
#define WW    56
#define HW    3136
#define KK2   2304      // CH*9
#define MEXP  8

#define BM 128
#define BN 128
#define BK 32
#define NCHUNK (KK2 / BK)          // 72
#define NPIX_T ((HW + BN - 1) / BN) // 25

// padded x: per (dw-plane, b*CH+c): 58 rows x 64 cols tf32
#define XROW   64
#define XCH    (58 * XROW)          // 3712
#define XPLANE (BATCH * CH * XCH)   // 30408704

// smem: A = 128 rows x 128B (XOR swizzle). B = 32 k-rows x 544B.
#define ATILE  (BM * 128)           // 16384
#define BROWB  544
#define BTILE  (BK * BROWB)         // 17408
#define STAGE  (ATILE + BTILE)      // 33792
#define NSTAGE 3
#define SMEM_BYTES (NSTAGE * STAGE) // 101376

// Scratch
__device__ float    g_gap[BATCH * CH];
__device__ float    g_alpha[BATCH * MEXP];
__device__ float    g_biasc[BATCH * CH];
__device__ uint32_t g_wt[(size_t)BATCH * CH * KK2];       // combined weights tf32 [b][o][k]
__device__ uint32_t g_xp[(size_t)3 * XPLANE + 4096];      // padded shifted x planes (+guard)

// per kernel-position r: plane + dh row offset (element units)
__constant__ int c_rtab[9] = {
    -XROW,              XPLANE - XROW,       2 * XPLANE - XROW,
    0,                  XPLANE,              2 * XPLANE,
    XROW,               XPLANE + XROW,       2 * XPLANE + XROW
};

// ---------------- helpers ----------------
__device__ __forceinline__ uint32_t smem_u32(const void* p) {
    uint32_t a;
    asm("{ .reg .u64 t; cvta.to.shared.u64 t, %1; cvt.u32.u64 %0, t; }" : "=r"(a) : "l"(p));
    return a;
}
__device__ __forceinline__ uint32_t f2tf32(float f) {
    uint32_t r; asm("cvt.rna.tf32.f32 %0, %1;" : "=r"(r) : "f"(f)); return r;
}
__device__ __forceinline__ void ldsm4(uint32_t& r0, uint32_t& r1, uint32_t& r2, uint32_t& r3,
                                      uint32_t addr) {
    asm volatile("ldmatrix.sync.aligned.m8n8.x4.shared.b16 {%0,%1,%2,%3}, [%4];"
                 : "=r"(r0), "=r"(r1), "=r"(r2), "=r"(r3) : "r"(addr));
}
__device__ __forceinline__ uint32_t lds32(uint32_t addr) {
    uint32_t v;
    asm volatile("ld.shared.b32 %0, [%1];" : "=r"(v) : "r"(addr));
    return v;
}
__device__ __forceinline__ void mma_tf32(float* c, const uint32_t* a, uint32_t b0, uint32_t b1) {
    asm volatile(
        "mma.sync.aligned.m16n8k8.row.col.f32.tf32.tf32.f32 "
        "{%0,%1,%2,%3}, {%4,%5,%6,%7}, {%8,%9}, {%0,%1,%2,%3};"
        : "+f"(c[0]), "+f"(c[1]), "+f"(c[2]), "+f"(c[3])
        : "r"(a[0]), "r"(a[1]), "r"(a[2]), "r"(a[3]), "r"(b0), "r"(b1));
}
__device__ __forceinline__ void cpasync16(uint32_t dst, const void* src) {
    asm volatile("cp.async.cg.shared.global [%0], [%1], 16;" :: "r"(dst), "l"(src) : "memory");
}

// ---------------------------------------------------------------------------
// 1) Fused xpad + GAP: one block per (b*CH+c). Reads x once; writes all 3
//    shifted tf32 planes; accumulates fp32 channel sum -> g_gap.
// ---------------------------------------------------------------------------
__global__ void xpad_gap_kernel(const float* __restrict__ x) {
    int bc = blockIdx.x;
    const float* xc = x + (size_t)bc * HW;
    uint4* dst0 = (uint4*)(g_xp + (size_t)bc * XCH);
    uint4* dst1 = (uint4*)(g_xp + (size_t)XPLANE + (size_t)bc * XCH);
    uint4* dst2 = (uint4*)(g_xp + (size_t)2 * XPLANE + (size_t)bc * XCH);

    float s = 0.f;
    for (int i4 = threadIdx.x; i4 < 58 * 16; i4 += 256) {
        int row = i4 >> 4;
        int wq  = (i4 & 15) * 4;
        int h   = row - 1;
        bool rv = (unsigned)h < HH;
        const float* xr = xc + h * WW;
        float v[6];
        #pragma unroll
        for (int jj = 0; jj < 6; jj++) {
            int w = wq - 1 + jj;
            v[jj] = (rv && (unsigned)w < WW) ? xr[w] : 0.f;
        }
        s += v[1] + v[2] + v[3] + v[4];    // centers: each x elem counted once
        uint32_t t[6];
        #pragma unroll
        for (int jj = 0; jj < 6; jj++) t[jj] = f2tf32(v[jj]);
        dst0[i4] = make_uint4(t[0], t[1], t[2], t[3]);
        dst1[i4] = make_uint4(t[1], t[2], t[3], t[4]);
        dst2[i4] = make_uint4(t[2], t[3], t[4], t[5]);
    }
    __shared__ float sm[8];
    #pragma unroll
    for (int off = 16; off; off >>= 1) s += __shfl_down_sync(0xffffffffu, s, off);
    if ((threadIdx.x & 31) == 0) sm[threadIdx.x >> 5] = s;
    __syncthreads();
    if (threadIdx.x == 0) {
        float tot = 0.f;
        #pragma unroll
        for (int q = 0; q < 8; q++) tot += sm[q];
        g_gap[bc] = tot * (1.f / (float)HW);
    }
}

// ---------------------------------------------------------------------------
// 2) Gate softmax + combined bias
// ---------------------------------------------------------------------------
__global__ void gate_kernel(const float* __restrict__ gate_w,
                            const float* __restrict__ gate_b,
                            const float* __restrict__ bias) {
    __shared__ float lg[BATCH][MEXP];
    __shared__ float al[BATCH][MEXP];
    int t = threadIdx.x;
    int b = t >> 3, m = t & 7;
    float acc = gate_b[m];
    const float* gp = &g_gap[b * CH];
    const float* gw = &gate_w[m * CH];
    for (int i = 0; i < CH; i++) acc += gp[i] * gw[i];
    lg[b][m] = acc;
    __syncthreads();
    if (t < BATCH) {
        float mx = lg[t][0];
        #pragma unroll
        for (int j = 1; j < MEXP; j++) mx = fmaxf(mx, lg[t][j]);
        float e[MEXP], s = 0.f;
        #pragma unroll
        for (int j = 0; j < MEXP; j++) { e[j] = expf(lg[t][j] - mx); s += e[j]; }
        float inv = 1.f / s;
        #pragma unroll
        for (int j = 0; j < MEXP; j++) { al[t][j] = e[j] * inv; g_alpha[t * MEXP + j] = e[j] * inv; }
    }
    __syncthreads();
    for (int b2 = 0; b2 < BATCH; b2++) {
        float s = 0.f;
        #pragma unroll
        for (int j = 0; j < MEXP; j++) s += al[b2][j] * bias[j * CH + t];
        g_biasc[b2 * CH + t] = s;
    }
}

// ---------------------------------------------------------------------------
// 3) Combine experts -> tf32, batch-tiled: read each expert value ONCE,
//    apply all 32 alpha vectors. grid 576, 256 threads.
// ---------------------------------------------------------------------------
__global__ void combine_kernel(const float* __restrict__ weight) {
    __shared__ float al[BATCH][MEXP];
    if (threadIdx.x < BATCH * MEXP)
        al[threadIdx.x >> 3][threadIdx.x & 7] = g_alpha[threadIdx.x];
    __syncthreads();

    size_t i4 = (size_t)blockIdx.x * 256 + threadIdx.x;   // float4 idx < 147456
    const size_t estride = (size_t)CH * KK2 / 4;          // float4s per expert
    float4 v[MEXP];
    #pragma unroll
    for (int m = 0; m < MEXP; m++)
        v[m] = ((const float4*)weight)[m * estride + i4];

    #pragma unroll 4
    for (int b = 0; b < BATCH; b++) {
        float4 acc = make_float4(0.f, 0.f, 0.f, 0.f);
        #pragma unroll
        for (int m = 0; m < MEXP; m++) {
            float a = al[b][m];
            acc.x += a * v[m].x; acc.y += a * v[m].y;
            acc.z += a * v[m].z; acc.w += a * v[m].w;
        }
        uint4 o;
        o.x = f2tf32(acc.x); o.y = f2tf32(acc.y);
        o.z = f2tf32(acc.z); o.w = f2tf32(acc.w);
        ((uint4*)g_wt)[b * estride + i4] = o;
    }
}

// ---------------------------------------------------------------------------
// 4) Conv GEMM (unchanged R15 winner): tf32 mma.sync m16n8k8,
//    128x128x32 tiles, 3-stage cp.async, one barrier per chunk.
// ---------------------------------------------------------------------------
__global__ void __launch_bounds__(256, 2)
conv_mma_kernel(float* __restrict__ out) {
    extern __shared__ char smem[];
    const uint32_t sbase = smem_u32(smem);
    const int tid  = threadIdx.x;
    const int wid  = tid >> 5;
    const int lane = tid & 31;
    const int warp_m = wid >> 1;
    const int warp_n = wid & 1;

    const int b  = blockIdx.z;
    const int o0 = blockIdx.y * BM;
    const int p0 = blockIdx.x * BN;
    const int bc0 = b * CH;

    const int aRowIn = lane >> 3;
    const int ag     = lane & 7;
    uint32_t aDst[4];
    const uint32_t* aSrc[4];
    #pragma unroll
    for (int q = 0; q < 4; q++) {
        int row = q * 32 + wid * 4 + aRowIn;
        aDst[q] = (uint32_t)row * 128 + (((uint32_t)(ag ^ (row & 7))) << 4);
        aSrc[q] = g_wt + ((size_t)(bc0 + o0 + row)) * KK2 + ag * 4;
    }

    int pB = p0 + lane * 4;
    int hB = pB / WW;
    const int pixoff = (hB + 1) * XROW + (pB - hB * WW);
    int rj[4], cj[4];
    #pragma unroll
    for (int j = 0; j < 4; j++) {
        int k0 = wid * 4 + j;
        cj[j] = k0 / 9;
        rj[j] = k0 - 9 * cj[j];
    }
    const uint32_t* xpb = g_xp + (size_t)bc0 * XCH;
    uint32_t bDst[4];
    #pragma unroll
    for (int j = 0; j < 4; j++)
        bDst[j] = ATILE + (uint32_t)(wid * 4 + j) * BROWB + (uint32_t)lane * 16;

    const uint32_t ls  = (uint32_t)(lane & 7);
    const uint32_t aHi = (uint32_t)(lane >> 4);
    const uint32_t aRow0 = (uint32_t)(warp_m * 32 + (lane & 15)) * 128;
    const uint32_t aRow1 = aRow0 + 16 * 128;
    const uint32_t bLane = ATILE + (uint32_t)(lane & 3) * BROWB
                         + (uint32_t)(warp_n * 64 + (lane >> 2)) * 4;

    float acc[2][8][4];
    #pragma unroll
    for (int h = 0; h < 2; h++)
        #pragma unroll
        for (int j = 0; j < 8; j++)
            #pragma unroll
            for (int q = 0; q < 4; q++) acc[h][j][q] = 0.f;

    auto issueStage = [&](int chunk, int s) {
        const uint32_t stg = sbase + s * STAGE;
        #pragma unroll
        for (int q = 0; q < 4; q++) cpasync16(stg + aDst[q], aSrc[q] + chunk * BK);
        #pragma unroll
        for (int j = 0; j < 4; j++) {
            const uint32_t* src = xpb + cj[j] * XCH + c_rtab[rj[j]] + pixoff;
            cpasync16(stg + bDst[j], src);
            rj[j] += 5;
            if (rj[j] >= 9) { rj[j] -= 9; cj[j] += 4; }
            else cj[j] += 3;
        }
        asm volatile("cp.async.commit_group;" ::: "memory");
    };

    issueStage(0, 0);
    issueStage(1, 1);

    int sIdx = 0;
    for (int c0 = 0; c0 < NCHUNK; c0++) {
        if (c0 + 1 < NCHUNK)
            asm volatile("cp.async.wait_group 1;" ::: "memory");
        else
            asm volatile("cp.async.wait_group 0;" ::: "memory");
        __syncthreads();
        if (c0 + 2 < NCHUNK) issueStage(c0 + 2, (sIdx + 2) % NSTAGE);

        const uint32_t stg = sbase + sIdx * STAGE;

        #pragma unroll
        for (int t = 0; t < 2; t++) {
            uint32_t a[2][2][4];
            ldsm4(a[0][0][0], a[0][0][1], a[0][0][2], a[0][0][3],
                  stg + aRow0 + (((4u * t + 0 + aHi) ^ ls) << 4));
            ldsm4(a[0][1][0], a[0][1][1], a[0][1][2], a[0][1][3],
                  stg + aRow0 + (((4u * t + 2 + aHi) ^ ls) << 4));
            ldsm4(a[1][0][0], a[1][0][1], a[1][0][2], a[1][0][3],
                  stg + aRow1 + (((4u * t + 0 + aHi) ^ ls) << 4));
            ldsm4(a[1][1][0], a[1][1][1], a[1][1][2], a[1][1][3],
                  stg + aRow1 + (((4u * t + 2 + aHi) ^ ls) << 4));
            const uint32_t bT = stg + bLane + (uint32_t)t * (16 * BROWB);
            #pragma unroll
            for (int half = 0; half < 2; half++) {
                uint32_t bb[4][4];
                #pragma unroll
                for (int q = 0; q < 4; q++) {
                    uint32_t a0 = bT + (uint32_t)(half * 4 + q) * 32;
                    bb[q][0] = lds32(a0);
                    bb[q][1] = lds32(a0 + 4 * BROWB);
                    bb[q][2] = lds32(a0 + 8 * BROWB);
                    bb[q][3] = lds32(a0 + 12 * BROWB);
                }
                #pragma unroll
                for (int h = 0; h < 2; h++) {
                    #pragma unroll
                    for (int q = 0; q < 4; q++)
                        mma_tf32(acc[h][half * 4 + q], a[h][0], bb[q][0], bb[q][1]);
                    #pragma unroll
                    for (int q = 0; q < 4; q++)
                        mma_tf32(acc[h][half * 4 + q], a[h][1], bb[q][2], bb[q][3]);
                }
            }
        }
        sIdx = (sIdx + 1) % NSTAGE;
    }

    #pragma unroll
    for (int h = 0; h < 2; h++) {
        int r0 = o0 + warp_m * 32 + h * 16 + (lane >> 2);
        float bi0 = g_biasc[b * CH + r0];
        float bi1 = g_biasc[b * CH + r0 + 8];
        float* out0 = out + ((size_t)b * CH + r0) * HW;
        float* out1 = out0 + 8 * HW;
        #pragma unroll
        for (int nb = 0; nb < 8; nb++) {
            int p = p0 + warp_n * 64 + nb * 8 + (lane & 3) * 2;
            if (p < HW) {
                *(float2*)(out0 + p) = make_float2(acc[h][nb][0] + bi0, acc[h][nb][1] + bi0);
                *(float2*)(out1 + p) = make_float2(acc[h][nb][2] + bi1, acc[h][nb][3] + bi1);
            }
        }
    }
}

// ---------------------------------------------------------------------------
extern "C" void kernel_launch(void* const* d_in, const int* in_sizes, int n_in,
                              void* d_out, int out_size) {
    const float* x      = (const float*)d_in[0];
    const float* weight = (const float*)d_in[1];
    const float* bias   = (const float*)d_in[2];
    const float* gate_w = (const float*)d_in[3];
    const float* gate_b = (const float*)d_in[4];
    float* out = (float*)d_out;

    cudaFuncSetAttribute(conv_mma_kernel,
                         cudaFuncAttributeMaxDynamicSharedMemorySize, SMEM_BYTES);

    xpad_gap_kernel<<<BATCH * CH, 256>>>(x);
    gate_kernel<<<1, 256>>>(gate_w, gate_b, bias);
    combine_kernel<<<CH * KK2 / 4 / 256, 256>>>(weight);
    conv_mma_kernel<<<dim3(NPIX_T, CH / BM, BATCH), 256, SMEM_BYTES>>>(out);
}